// round 1
// baseline (speedup 1.0000x reference)
#include <cuda_runtime.h>
#include <cuda_bf16.h>
#include <math.h>

// Problem constants
#define BB   2
#define SS   2048
#define HID  2048
#define NH   16
#define NKV  4
#define HD   128
#define MTOK (BB*SS)          // 4096 tokens
#define QDIM (NH*HD)          // 2048
#define KVDIM (NKV*HD)        // 512

// ---------------------------------------------------------------------------
// Scratch buffers (no allocation allowed -> device globals)
// ---------------------------------------------------------------------------
__device__ float g_Q[(size_t)MTOK * QDIM];   // 33.5 MB
__device__ float g_K[(size_t)MTOK * KVDIM];  //  8.4 MB
__device__ float g_V[(size_t)MTOK * KVDIM];  //  8.4 MB
__device__ float g_O[(size_t)MTOK * QDIM];   // 33.5 MB

// ---------------------------------------------------------------------------
// SGEMM: C[M,N] = A[M,K] @ W[N,K]^T   (all row-major, fp32)
// 128x128 block, BK=8, 256 threads, 8x8 per-thread register tile.
// Requires M%128==0, N%128==0, K%8==0 (true for all uses here).
// ---------------------------------------------------------------------------
__global__ __launch_bounds__(256) void sgemm_abt(
    const float* __restrict__ A, const float* __restrict__ W,
    float* __restrict__ C, int M, int N, int K)
{
    const int BM = 128, BN = 128, BK = 8;
    __shared__ float As[BK][BM];
    __shared__ float Bs[BK][BN];

    const int bm = blockIdx.y * BM;
    const int bn = blockIdx.x * BN;
    const int tid = threadIdx.x;

    // global->shared load mapping: 128 rows x 8 k, one float4 per thread
    const int lr = tid >> 1;            // 0..127
    const int lc = (tid & 1) * 4;       // 0 or 4

    const int tx = tid & 15;            // 0..15 (N direction)
    const int ty = tid >> 4;            // 0..15 (M direction)

    const float* Ap = A + (size_t)(bm + lr) * K + lc;
    const float* Wp = W + (size_t)(bn + lr) * K + lc;

    float acc[8][8];
#pragma unroll
    for (int i = 0; i < 8; i++)
#pragma unroll
        for (int j = 0; j < 8; j++) acc[i][j] = 0.f;

    for (int k0 = 0; k0 < K; k0 += BK) {
        float4 av = *(const float4*)(Ap + k0);
        float4 wv = *(const float4*)(Wp + k0);
        As[lc + 0][lr] = av.x; As[lc + 1][lr] = av.y;
        As[lc + 2][lr] = av.z; As[lc + 3][lr] = av.w;
        Bs[lc + 0][lr] = wv.x; Bs[lc + 1][lr] = wv.y;
        Bs[lc + 2][lr] = wv.z; Bs[lc + 3][lr] = wv.w;
        __syncthreads();

#pragma unroll
        for (int k = 0; k < BK; k++) {
            float ar[8], br[8];
            *(float4*)&ar[0] = *(const float4*)&As[k][ty * 8];
            *(float4*)&ar[4] = *(const float4*)&As[k][ty * 8 + 4];
            *(float4*)&br[0] = *(const float4*)&Bs[k][tx * 8];
            *(float4*)&br[4] = *(const float4*)&Bs[k][tx * 8 + 4];
#pragma unroll
            for (int i = 0; i < 8; i++)
#pragma unroll
                for (int j = 0; j < 8; j++)
                    acc[i][j] = fmaf(ar[i], br[j], acc[i][j]);
        }
        __syncthreads();
    }

#pragma unroll
    for (int i = 0; i < 8; i++) {
        float* Cp = C + (size_t)(bm + ty * 8 + i) * N + bn + tx * 8;
        *(float4*)(Cp)     = make_float4(acc[i][0], acc[i][1], acc[i][2], acc[i][3]);
        *(float4*)(Cp + 4) = make_float4(acc[i][4], acc[i][5], acc[i][6], acc[i][7]);
    }
}

// ---------------------------------------------------------------------------
// RoPE in-place on X[MTOK][nheads*128]. Pair (i, i+64), angle = pos * theta^(-i/64)
// ---------------------------------------------------------------------------
__global__ void rope_kernel(float* __restrict__ X,
                            const int* __restrict__ pos_ids, int nheads)
{
    int idx = blockIdx.x * blockDim.x + threadIdx.x;
    int total = MTOK * nheads * 64;
    if (idx >= total) return;
    int i = idx & 63;
    int h = (idx >> 6) % nheads;
    int m = idx / (64 * nheads);
    int pos = pos_ids[m];

    // ln(10000)/64
    double inv = exp(-(double)i * 0.14391156831212787);
    double ang = (double)pos * inv;
    double sv, cv;
    sincos(ang, &sv, &cv);
    float c = (float)cv, s = (float)sv;

    size_t base = (size_t)m * (nheads * 128) + h * 128 + i;
    float x1 = X[base];
    float x2 = X[base + 64];
    X[base]      = x1 * c - x2 * s;
    X[base + 64] = x2 * c + x1 * s;
}

// ---------------------------------------------------------------------------
// Flash attention (fp32, causal, GQA). 64 q-rows x 64 k-cols tiles, 256 thr.
// Thread (ty,tx): scores 4x4 (rows ty*4+rr, cols tx*4+jj), O accum 4x8
// (rows ty*4+rr, cols tx*8+cc). P staged through smem for the PV product.
// dyn smem: Qs(32K) Ks(32K) Vs(32K) Ps(16K) = 112 KB
// ---------------------------------------------------------------------------
__global__ __launch_bounds__(256) void flash_kernel(
    const float* __restrict__ Q, const float* __restrict__ K,
    const float* __restrict__ V, float* __restrict__ O)
{
    extern __shared__ float sm[];
    float* Qs = sm;                 // [64][128]
    float* Ks = sm + 64 * 128;      // [64][128]
    float* Vs = sm + 2 * 64 * 128;  // [64][128]
    float* Ps = sm + 3 * 64 * 128;  // [64][64]

    const int q0 = blockIdx.x * 64;
    const int h  = blockIdx.y;
    const int b  = blockIdx.z;
    const int kvh = h >> 2;          // NH/NKV = 4
    const int tid = threadIdx.x;
    const int tx = tid & 15, ty = tid >> 4;

    // Load Q tile (rows q0..q0+63 of head h)
    for (int i = tid; i < 64 * 128 / 4; i += 256) {
        int r = i >> 5;              // 32 float4 per row
        int c = (i & 31) << 2;
        ((float4*)Qs)[i] =
            *(const float4*)(Q + (size_t)(b * SS + q0 + r) * QDIM + h * HD + c);
    }

    float acc[4][8];
#pragma unroll
    for (int a = 0; a < 4; a++)
#pragma unroll
        for (int c = 0; c < 8; c++) acc[a][c] = 0.f;
    float mrow[4] = {-1e30f, -1e30f, -1e30f, -1e30f};
    float lrow[4] = {0.f, 0.f, 0.f, 0.f};
    const float scale = 0.08838834764831845f;  // 1/sqrt(128)

    for (int kt = 0; kt <= q0; kt += 64) {
        __syncthreads();  // prev PV done with Ks/Vs/Ps
        for (int i = tid; i < 64 * 128 / 4; i += 256) {
            int r = i >> 5;
            int c = (i & 31) << 2;
            size_t base = (size_t)(b * SS + kt + r) * KVDIM + kvh * HD + c;
            ((float4*)Ks)[i] = *(const float4*)(K + base);
            ((float4*)Vs)[i] = *(const float4*)(V + base);
        }
        __syncthreads();

        // S = Q K^T (4x4 per thread)
        float s[4][4];
#pragma unroll
        for (int a = 0; a < 4; a++)
#pragma unroll
            for (int j = 0; j < 4; j++) s[a][j] = 0.f;

        for (int d = 0; d < 128; d += 4) {
            float4 qv[4], kv[4];
#pragma unroll
            for (int rr = 0; rr < 4; rr++)
                qv[rr] = *(const float4*)(Qs + (ty * 4 + rr) * 128 + d);
#pragma unroll
            for (int jj = 0; jj < 4; jj++)
                kv[jj] = *(const float4*)(Ks + (tx * 4 + jj) * 128 + d);
#pragma unroll
            for (int rr = 0; rr < 4; rr++)
#pragma unroll
                for (int jj = 0; jj < 4; jj++) {
                    s[rr][jj] = fmaf(qv[rr].x, kv[jj].x, s[rr][jj]);
                    s[rr][jj] = fmaf(qv[rr].y, kv[jj].y, s[rr][jj]);
                    s[rr][jj] = fmaf(qv[rr].z, kv[jj].z, s[rr][jj]);
                    s[rr][jj] = fmaf(qv[rr].w, kv[jj].w, s[rr][jj]);
                }
        }

        // mask + online softmax update
#pragma unroll
        for (int rr = 0; rr < 4; rr++) {
            int qg = q0 + ty * 4 + rr;
            float rowm = -1e30f;
#pragma unroll
            for (int jj = 0; jj < 4; jj++) {
                int kg = kt + tx * 4 + jj;
                s[rr][jj] = (kg <= qg) ? s[rr][jj] * scale : -1e30f;
                rowm = fmaxf(rowm, s[rr][jj]);
            }
            rowm = fmaxf(rowm, __shfl_xor_sync(0xffffffffu, rowm, 8));
            rowm = fmaxf(rowm, __shfl_xor_sync(0xffffffffu, rowm, 4));
            rowm = fmaxf(rowm, __shfl_xor_sync(0xffffffffu, rowm, 2));
            rowm = fmaxf(rowm, __shfl_xor_sync(0xffffffffu, rowm, 1));
            float mnew  = fmaxf(mrow[rr], rowm);
            float alpha = expf(mrow[rr] - mnew);
            float rsum = 0.f;
#pragma unroll
            for (int jj = 0; jj < 4; jj++) {
                float p = expf(s[rr][jj] - mnew);
                Ps[(ty * 4 + rr) * 64 + tx * 4 + jj] = p;
                rsum += p;
            }
            rsum += __shfl_xor_sync(0xffffffffu, rsum, 8);
            rsum += __shfl_xor_sync(0xffffffffu, rsum, 4);
            rsum += __shfl_xor_sync(0xffffffffu, rsum, 2);
            rsum += __shfl_xor_sync(0xffffffffu, rsum, 1);
            lrow[rr] = lrow[rr] * alpha + rsum;
            mrow[rr] = mnew;
#pragma unroll
            for (int cc = 0; cc < 8; cc++) acc[rr][cc] *= alpha;
        }
        __syncthreads();  // Ps fully written

        // O += P V  (cols tx*8..tx*8+7)
        for (int j = 0; j < 64; j += 4) {
            float4 p4[4];
#pragma unroll
            for (int rr = 0; rr < 4; rr++)
                p4[rr] = *(const float4*)(Ps + (ty * 4 + rr) * 64 + j);
#pragma unroll
            for (int jj = 0; jj < 4; jj++) {
                float4 v0 = *(const float4*)(Vs + (j + jj) * 128 + tx * 8);
                float4 v1 = *(const float4*)(Vs + (j + jj) * 128 + tx * 8 + 4);
#pragma unroll
                for (int rr = 0; rr < 4; rr++) {
                    float p = (jj == 0) ? p4[rr].x : (jj == 1) ? p4[rr].y
                             : (jj == 2) ? p4[rr].z : p4[rr].w;
                    acc[rr][0] = fmaf(p, v0.x, acc[rr][0]);
                    acc[rr][1] = fmaf(p, v0.y, acc[rr][1]);
                    acc[rr][2] = fmaf(p, v0.z, acc[rr][2]);
                    acc[rr][3] = fmaf(p, v0.w, acc[rr][3]);
                    acc[rr][4] = fmaf(p, v1.x, acc[rr][4]);
                    acc[rr][5] = fmaf(p, v1.y, acc[rr][5]);
                    acc[rr][6] = fmaf(p, v1.z, acc[rr][6]);
                    acc[rr][7] = fmaf(p, v1.w, acc[rr][7]);
                }
            }
        }
    }

    // epilogue: normalize and store into [token][h*HD + d] layout
#pragma unroll
    for (int rr = 0; rr < 4; rr++) {
        float inv = 1.f / lrow[rr];
        size_t base = (size_t)(b * SS + q0 + ty * 4 + rr) * QDIM + h * HD + tx * 8;
        *(float4*)(O + base) =
            make_float4(acc[rr][0] * inv, acc[rr][1] * inv, acc[rr][2] * inv, acc[rr][3] * inv);
        *(float4*)(O + base + 4) =
            make_float4(acc[rr][4] * inv, acc[rr][5] * inv, acc[rr][6] * inv, acc[rr][7] * inv);
    }
}

// ---------------------------------------------------------------------------
// kernel_launch: qkv gemms -> rope -> flash -> output gemm
// ---------------------------------------------------------------------------
extern "C" void kernel_launch(void* const* d_in, const int* in_sizes, int n_in,
                              void* d_out, int out_size)
{
    const float* hidden = (const float*)d_in[0];
    const float* Wq     = (const float*)d_in[1];
    const float* Wk     = (const float*)d_in[2];
    const float* Wv     = (const float*)d_in[3];
    const float* Wo     = (const float*)d_in[4];
    const int*   pos    = (const int*)d_in[5];
    float* out = (float*)d_out;

    float *Qb, *Kb, *Vb, *Ob;
    cudaGetSymbolAddress((void**)&Qb, g_Q);
    cudaGetSymbolAddress((void**)&Kb, g_K);
    cudaGetSymbolAddress((void**)&Vb, g_V);
    cudaGetSymbolAddress((void**)&Ob, g_O);

    dim3 thr(256);
    // QKV projections
    sgemm_abt<<<dim3(QDIM / 128, MTOK / 128), thr>>>(hidden, Wq, Qb, MTOK, QDIM, HID);
    sgemm_abt<<<dim3(KVDIM / 128, MTOK / 128), thr>>>(hidden, Wk, Kb, MTOK, KVDIM, HID);
    sgemm_abt<<<dim3(KVDIM / 128, MTOK / 128), thr>>>(hidden, Wv, Vb, MTOK, KVDIM, HID);

    // RoPE on Q and K
    rope_kernel<<<(MTOK * NH * 64) / 256, 256>>>(Qb, pos, NH);
    rope_kernel<<<(MTOK * NKV * 64) / 256, 256>>>(Kb, pos, NKV);

    // Flash attention
    cudaFuncSetAttribute(flash_kernel,
                         cudaFuncAttributeMaxDynamicSharedMemorySize, 114688);
    flash_kernel<<<dim3(SS / 64, NH, BB), 256, 114688>>>(Qb, Kb, Vb, Ob);

    // Output projection
    sgemm_abt<<<dim3(HID / 128, MTOK / 128), thr>>>(Ob, Wo, out, MTOK, HID, QDIM);
}

// round 3
// speedup vs baseline: 1.5081x; 1.5081x over previous
#include <cuda_runtime.h>
#include <cuda_bf16.h>
#include <math.h>
#include <stdint.h>

// Problem constants
#define BB   2
#define SS   2048
#define HID  2048
#define NH   16
#define NKV  4
#define HD   128
#define MTOK (BB*SS)          // 4096 tokens
#define QDIM (NH*HD)          // 2048
#define KVDIM (NKV*HD)        // 512

// ---------------------------------------------------------------------------
// Scratch (no allocation allowed -> device globals)
// ---------------------------------------------------------------------------
__device__ float g_Q[(size_t)MTOK * QDIM];
__device__ float g_K[(size_t)MTOK * KVDIM];
__device__ float g_V[(size_t)MTOK * KVDIM];
__device__ float g_O[(size_t)MTOK * QDIM];

// ---------------------------------------------------------------------------
// helpers
// ---------------------------------------------------------------------------
__device__ __forceinline__ uint32_t smem_to_u32(const void* p) {
    uint32_t a;
    asm("{ .reg .u64 t; cvta.to.shared.u64 t, %1; cvt.u32.u64 %0, t; }"
        : "=r"(a) : "l"(p));
    return a;
}

__device__ __forceinline__ uint32_t pack_bf16(__nv_bfloat16 a, __nv_bfloat16 b) {
    return (uint32_t)__bfloat16_as_ushort(a) |
           ((uint32_t)__bfloat16_as_ushort(b) << 16);
}

// split float4 into bf16 hi (8 msb mantissa) and bf16 lo (next 8 bits)
__device__ __forceinline__ void split4(float4 v, uint2& h, uint2& l) {
    __nv_bfloat16 h0 = __float2bfloat16_rn(v.x);
    __nv_bfloat16 h1 = __float2bfloat16_rn(v.y);
    __nv_bfloat16 h2 = __float2bfloat16_rn(v.z);
    __nv_bfloat16 h3 = __float2bfloat16_rn(v.w);
    __nv_bfloat16 l0 = __float2bfloat16_rn(v.x - __bfloat162float(h0));
    __nv_bfloat16 l1 = __float2bfloat16_rn(v.y - __bfloat162float(h1));
    __nv_bfloat16 l2 = __float2bfloat16_rn(v.z - __bfloat162float(h2));
    __nv_bfloat16 l3 = __float2bfloat16_rn(v.w - __bfloat162float(h3));
    h.x = pack_bf16(h0, h1); h.y = pack_bf16(h2, h3);
    l.x = pack_bf16(l0, l1); l.y = pack_bf16(l2, l3);
}

#define LDMX4(r, addr) \
    asm volatile("ldmatrix.sync.aligned.m8n8.x4.shared.b16 {%0,%1,%2,%3}, [%4];" \
        : "=r"((r)[0]), "=r"((r)[1]), "=r"((r)[2]), "=r"((r)[3]) : "r"(addr))

#define MMA_BF16(c, a, b0, b1) \
    asm volatile("mma.sync.aligned.m16n8k16.row.col.f32.bf16.bf16.f32 " \
        "{%0,%1,%2,%3},{%4,%5,%6,%7},{%8,%9},{%0,%1,%2,%3};" \
        : "+f"((c)[0]), "+f"((c)[1]), "+f"((c)[2]), "+f"((c)[3]) \
        : "r"((a)[0]), "r"((a)[1]), "r"((a)[2]), "r"((a)[3]), "r"(b0), "r"(b1))

// ---------------------------------------------------------------------------
// bf16x3 tensor-core GEMM: C[M,N] = A[M,K] @ W[N,K]^T, fp32 in/out.
// C = Ah*Bh + Ah*Bl + Al*Bh  (bf16 split, fp32 accum) -> ~1e-5 rel err.
// CTA tile 128x128, BK=32, 256 threads (8 warps, warp tile 64x32).
// smem: padded rows of 40 bf16 (80B), parts Ah|Al|Bh|Bl, double buffered.
// Requires M%128==0, N%128==0, K%32==0.
// ---------------------------------------------------------------------------
#define SROW   40                      // bf16 elems per smem row (32 + 8 pad)
#define TPART  (128 * SROW * 2)        // 10240 B per matrix part
#define TSTAGE (4 * TPART)             // 40960 B per stage
#define GEMM_SMEM (2 * TSTAGE)         // 81920 B

__global__ __launch_bounds__(256) void gemm_bf16x3(
    const float* __restrict__ A, const float* __restrict__ W,
    float* __restrict__ C, int M, int N, int K)
{
    extern __shared__ char smem[];
    const uint32_t sbase = smem_to_u32(smem);

    const int tid  = threadIdx.x;
    const int wid  = tid >> 5;
    const int lane = tid & 31;
    const int wm   = wid >> 2;     // 0..1  -> 64 rows
    const int wn   = wid & 3;      // 0..3  -> 32 cols
    const int bm   = blockIdx.y * 128;
    const int bn   = blockIdx.x * 128;

    // global load mapping: 4 groups of 32 rows, one float4 each
    const int lrow = tid >> 3;        // 0..31
    const int lcol = (tid & 7) * 4;   // 0,4,..28

    const int NKT = K / 32;

    float acc[4][4][4];
#pragma unroll
    for (int mf = 0; mf < 4; mf++)
#pragma unroll
        for (int nf = 0; nf < 4; nf++)
#pragma unroll
            for (int r = 0; r < 4; r++) acc[mf][nf][r] = 0.f;

    float4 a4[4], w4[4];

    // ---- prologue: load + store k-tile 0
#pragma unroll
    for (int g = 0; g < 4; g++) {
        a4[g] = *(const float4*)(A + (size_t)(bm + g * 32 + lrow) * K + lcol);
        w4[g] = *(const float4*)(W + (size_t)(bn + g * 32 + lrow) * K + lcol);
    }
    {
        char* p = smem;  // buf 0
#pragma unroll
        for (int g = 0; g < 4; g++) {
            int off = (g * 32 + lrow) * (SROW * 2) + lcol * 2;
            uint2 h, l;
            split4(a4[g], h, l);
            *(uint2*)(p + off)         = h;
            *(uint2*)(p + TPART + off) = l;
            split4(w4[g], h, l);
            *(uint2*)(p + 2 * TPART + off) = h;
            *(uint2*)(p + 3 * TPART + off) = l;
        }
    }
    __syncthreads();

    // lane-level ldmatrix byte offsets (within a matrix part)
    const int lr16 = lane & 15;
    const int lh   = lane >> 4;
    const uint32_t a_lane = (uint32_t)((wm * 64 + lr16) * (SROW * 2) + lh * 16);
    const uint32_t b_lane = (uint32_t)((wn * 32 + lr16) * (SROW * 2) + lh * 16);

    for (int kt = 0; kt < NKT; kt++) {
        // prefetch next k-tile into registers
        if (kt + 1 < NKT) {
            int k0 = (kt + 1) * 32;
#pragma unroll
            for (int g = 0; g < 4; g++) {
                a4[g] = *(const float4*)(A + (size_t)(bm + g * 32 + lrow) * K + k0 + lcol);
                w4[g] = *(const float4*)(W + (size_t)(bn + g * 32 + lrow) * K + k0 + lcol);
            }
        }

        // compute on buffer kt&1
        {
            const uint32_t base = sbase + (uint32_t)(kt & 1) * TSTAGE;
#pragma unroll
            for (int ks = 0; ks < 2; ks++) {
                const uint32_t kb = ks * 32;   // 16 bf16 = 32 bytes
                uint32_t ah[4][4], al[4][4], bh[2][4], bl[2][4];
#pragma unroll
                for (int mf = 0; mf < 4; mf++)
                    LDMX4(ah[mf], base + a_lane + mf * 16 * (SROW * 2) + kb);
#pragma unroll
                for (int nf2 = 0; nf2 < 2; nf2++)
                    LDMX4(bh[nf2], base + 2 * TPART + b_lane + nf2 * 16 * (SROW * 2) + kb);
                // pass 1: Ah * Bh
#pragma unroll
                for (int mf = 0; mf < 4; mf++)
#pragma unroll
                    for (int nf = 0; nf < 4; nf++)
                        MMA_BF16(acc[mf][nf], ah[mf],
                                 bh[nf >> 1][nf & 1], bh[nf >> 1][(nf & 1) + 2]);
                // pass 2: Ah * Bl
#pragma unroll
                for (int nf2 = 0; nf2 < 2; nf2++)
                    LDMX4(bl[nf2], base + 3 * TPART + b_lane + nf2 * 16 * (SROW * 2) + kb);
#pragma unroll
                for (int mf = 0; mf < 4; mf++)
#pragma unroll
                    for (int nf = 0; nf < 4; nf++)
                        MMA_BF16(acc[mf][nf], ah[mf],
                                 bl[nf >> 1][nf & 1], bl[nf >> 1][(nf & 1) + 2]);
                // pass 3: Al * Bh
#pragma unroll
                for (int mf = 0; mf < 4; mf++)
                    LDMX4(al[mf], base + TPART + a_lane + mf * 16 * (SROW * 2) + kb);
#pragma unroll
                for (int mf = 0; mf < 4; mf++)
#pragma unroll
                    for (int nf = 0; nf < 4; nf++)
                        MMA_BF16(acc[mf][nf], al[mf],
                                 bh[nf >> 1][nf & 1], bh[nf >> 1][(nf & 1) + 2]);
            }
        }

        // store next tile into the other buffer
        if (kt + 1 < NKT) {
            char* p = smem + ((kt + 1) & 1) * TSTAGE;
#pragma unroll
            for (int g = 0; g < 4; g++) {
                int off = (g * 32 + lrow) * (SROW * 2) + lcol * 2;
                uint2 h, l;
                split4(a4[g], h, l);
                *(uint2*)(p + off)         = h;
                *(uint2*)(p + TPART + off) = l;
                split4(w4[g], h, l);
                *(uint2*)(p + 2 * TPART + off) = h;
                *(uint2*)(p + 3 * TPART + off) = l;
            }
        }
        __syncthreads();
    }

    // epilogue: accum layout: c0,c1 -> (row lane/4, col 2*(lane%4)), c2,c3 -> row+8
    const int erow = bm + wm * 64 + (lane >> 2);
    const int ecol = bn + wn * 32 + (lane & 3) * 2;
#pragma unroll
    for (int mf = 0; mf < 4; mf++)
#pragma unroll
        for (int nf = 0; nf < 4; nf++) {
            float* c = acc[mf][nf];
            size_t r0 = (size_t)(erow + mf * 16) * N + ecol + nf * 8;
            size_t r1 = r0 + 8 * (size_t)N;
            *(float2*)(C + r0) = make_float2(c[0], c[1]);
            *(float2*)(C + r1) = make_float2(c[2], c[3]);
        }
}

// ---------------------------------------------------------------------------
// RoPE: one thread per (token, freq-pair), loops over heads.
// ---------------------------------------------------------------------------
__global__ void rope_kernel(float* __restrict__ X,
                            const int* __restrict__ pos_ids, int nheads)
{
    int idx = blockIdx.x * blockDim.x + threadIdx.x;
    if (idx >= MTOK * 64) return;
    int i = idx & 63;
    int m = idx >> 6;
    int p = pos_ids[m];

    double inv = exp(-(double)i * 0.14391156831212787);  // ln(10000)/64
    double ang = (double)p * inv;
    double k = rint(ang * 0.15915494309189535);          // 1/(2*pi)
    float r = (float)(ang - k * 6.283185307179586477);
    float sv, cv;
    sincosf(r, &sv, &cv);

    float* xp = X + (size_t)m * (nheads * 128) + i;
#pragma unroll 4
    for (int h = 0; h < nheads; h++) {
        float x1 = xp[0], x2 = xp[64];
        xp[0]  = x1 * cv - x2 * sv;
        xp[64] = x2 * cv + x1 * sv;
        xp += 128;
    }
}

// ---------------------------------------------------------------------------
// Flash attention (fp32, causal, GQA) — unchanged from round 1 (passing).
// ---------------------------------------------------------------------------
__global__ __launch_bounds__(256) void flash_kernel(
    const float* __restrict__ Q, const float* __restrict__ K,
    const float* __restrict__ V, float* __restrict__ O)
{
    extern __shared__ float sm[];
    float* Qs = sm;
    float* Ks = sm + 64 * 128;
    float* Vs = sm + 2 * 64 * 128;
    float* Ps = sm + 3 * 64 * 128;

    const int q0 = blockIdx.x * 64;
    const int h  = blockIdx.y;
    const int b  = blockIdx.z;
    const int kvh = h >> 2;
    const int tid = threadIdx.x;
    const int tx = tid & 15, ty = tid >> 4;

    for (int i = tid; i < 64 * 128 / 4; i += 256) {
        int r = i >> 5;
        int c = (i & 31) << 2;
        ((float4*)Qs)[i] =
            *(const float4*)(Q + (size_t)(b * SS + q0 + r) * QDIM + h * HD + c);
    }

    float acc[4][8];
#pragma unroll
    for (int a = 0; a < 4; a++)
#pragma unroll
        for (int c = 0; c < 8; c++) acc[a][c] = 0.f;
    float mrow[4] = {-1e30f, -1e30f, -1e30f, -1e30f};
    float lrow[4] = {0.f, 0.f, 0.f, 0.f};
    const float scale = 0.08838834764831845f;

    for (int kt = 0; kt <= q0; kt += 64) {
        __syncthreads();
        for (int i = tid; i < 64 * 128 / 4; i += 256) {
            int r = i >> 5;
            int c = (i & 31) << 2;
            size_t base = (size_t)(b * SS + kt + r) * KVDIM + kvh * HD + c;
            ((float4*)Ks)[i] = *(const float4*)(K + base);
            ((float4*)Vs)[i] = *(const float4*)(V + base);
        }
        __syncthreads();

        float s[4][4];
#pragma unroll
        for (int a = 0; a < 4; a++)
#pragma unroll
            for (int j = 0; j < 4; j++) s[a][j] = 0.f;

        for (int d = 0; d < 128; d += 4) {
            float4 qv[4], kv[4];
#pragma unroll
            for (int rr = 0; rr < 4; rr++)
                qv[rr] = *(const float4*)(Qs + (ty * 4 + rr) * 128 + d);
#pragma unroll
            for (int jj = 0; jj < 4; jj++)
                kv[jj] = *(const float4*)(Ks + (tx * 4 + jj) * 128 + d);
#pragma unroll
            for (int rr = 0; rr < 4; rr++)
#pragma unroll
                for (int jj = 0; jj < 4; jj++) {
                    s[rr][jj] = fmaf(qv[rr].x, kv[jj].x, s[rr][jj]);
                    s[rr][jj] = fmaf(qv[rr].y, kv[jj].y, s[rr][jj]);
                    s[rr][jj] = fmaf(qv[rr].z, kv[jj].z, s[rr][jj]);
                    s[rr][jj] = fmaf(qv[rr].w, kv[jj].w, s[rr][jj]);
                }
        }

#pragma unroll
        for (int rr = 0; rr < 4; rr++) {
            int qg = q0 + ty * 4 + rr;
            float rowm = -1e30f;
#pragma unroll
            for (int jj = 0; jj < 4; jj++) {
                int kg = kt + tx * 4 + jj;
                s[rr][jj] = (kg <= qg) ? s[rr][jj] * scale : -1e30f;
                rowm = fmaxf(rowm, s[rr][jj]);
            }
            rowm = fmaxf(rowm, __shfl_xor_sync(0xffffffffu, rowm, 8));
            rowm = fmaxf(rowm, __shfl_xor_sync(0xffffffffu, rowm, 4));
            rowm = fmaxf(rowm, __shfl_xor_sync(0xffffffffu, rowm, 2));
            rowm = fmaxf(rowm, __shfl_xor_sync(0xffffffffu, rowm, 1));
            float mnew  = fmaxf(mrow[rr], rowm);
            float alpha = expf(mrow[rr] - mnew);
            float rsum = 0.f;
#pragma unroll
            for (int jj = 0; jj < 4; jj++) {
                float p = expf(s[rr][jj] - mnew);
                Ps[(ty * 4 + rr) * 64 + tx * 4 + jj] = p;
                rsum += p;
            }
            rsum += __shfl_xor_sync(0xffffffffu, rsum, 8);
            rsum += __shfl_xor_sync(0xffffffffu, rsum, 4);
            rsum += __shfl_xor_sync(0xffffffffu, rsum, 2);
            rsum += __shfl_xor_sync(0xffffffffu, rsum, 1);
            lrow[rr] = lrow[rr] * alpha + rsum;
            mrow[rr] = mnew;
#pragma unroll
            for (int cc = 0; cc < 8; cc++) acc[rr][cc] *= alpha;
        }
        __syncthreads();

        for (int j = 0; j < 64; j += 4) {
            float4 p4[4];
#pragma unroll
            for (int rr = 0; rr < 4; rr++)
                p4[rr] = *(const float4*)(Ps + (ty * 4 + rr) * 64 + j);
#pragma unroll
            for (int jj = 0; jj < 4; jj++) {
                float4 v0 = *(const float4*)(Vs + (j + jj) * 128 + tx * 8);
                float4 v1 = *(const float4*)(Vs + (j + jj) * 128 + tx * 8 + 4);
#pragma unroll
                for (int rr = 0; rr < 4; rr++) {
                    float p = (jj == 0) ? p4[rr].x : (jj == 1) ? p4[rr].y
                             : (jj == 2) ? p4[rr].z : p4[rr].w;
                    acc[rr][0] = fmaf(p, v0.x, acc[rr][0]);
                    acc[rr][1] = fmaf(p, v0.y, acc[rr][1]);
                    acc[rr][2] = fmaf(p, v0.z, acc[rr][2]);
                    acc[rr][3] = fmaf(p, v0.w, acc[rr][3]);
                    acc[rr][4] = fmaf(p, v1.x, acc[rr][4]);
                    acc[rr][5] = fmaf(p, v1.y, acc[rr][5]);
                    acc[rr][6] = fmaf(p, v1.z, acc[rr][6]);
                    acc[rr][7] = fmaf(p, v1.w, acc[rr][7]);
                }
            }
        }
    }

#pragma unroll
    for (int rr = 0; rr < 4; rr++) {
        float inv = 1.f / lrow[rr];
        size_t base = (size_t)(b * SS + q0 + ty * 4 + rr) * QDIM + h * HD + tx * 8;
        *(float4*)(O + base) =
            make_float4(acc[rr][0] * inv, acc[rr][1] * inv, acc[rr][2] * inv, acc[rr][3] * inv);
        *(float4*)(O + base + 4) =
            make_float4(acc[rr][4] * inv, acc[rr][5] * inv, acc[rr][6] * inv, acc[rr][7] * inv);
    }
}

// ---------------------------------------------------------------------------
// launcher
// ---------------------------------------------------------------------------
extern "C" void kernel_launch(void* const* d_in, const int* in_sizes, int n_in,
                              void* d_out, int out_size)
{
    const float* hidden = (const float*)d_in[0];
    const float* Wq     = (const float*)d_in[1];
    const float* Wk     = (const float*)d_in[2];
    const float* Wv     = (const float*)d_in[3];
    const float* Wo     = (const float*)d_in[4];
    const int*   pos    = (const int*)d_in[5];
    float* out = (float*)d_out;

    float *Qb, *Kb, *Vb, *Ob;
    cudaGetSymbolAddress((void**)&Qb, g_Q);
    cudaGetSymbolAddress((void**)&Kb, g_K);
    cudaGetSymbolAddress((void**)&Vb, g_V);
    cudaGetSymbolAddress((void**)&Ob, g_O);

    cudaFuncSetAttribute(gemm_bf16x3,
                         cudaFuncAttributeMaxDynamicSharedMemorySize, GEMM_SMEM);
    cudaFuncSetAttribute(flash_kernel,
                         cudaFuncAttributeMaxDynamicSharedMemorySize, 114688);

    // QKV projections (tensor-core bf16x3)
    gemm_bf16x3<<<dim3(QDIM / 128, MTOK / 128), 256, GEMM_SMEM>>>(hidden, Wq, Qb, MTOK, QDIM, HID);
    gemm_bf16x3<<<dim3(KVDIM / 128, MTOK / 128), 256, GEMM_SMEM>>>(hidden, Wk, Kb, MTOK, KVDIM, HID);
    gemm_bf16x3<<<dim3(KVDIM / 128, MTOK / 128), 256, GEMM_SMEM>>>(hidden, Wv, Vb, MTOK, KVDIM, HID);

    // RoPE
    rope_kernel<<<(MTOK * 64) / 256, 256>>>(Qb, pos, NH);
    rope_kernel<<<(MTOK * 64) / 256, 256>>>(Kb, pos, NKV);

    // Flash attention (fp32)
    flash_kernel<<<dim3(SS / 64, NH, BB), 256, 114688>>>(Qb, Kb, Vb, Ob);

    // Output projection
    gemm_bf16x3<<<dim3(HID / 128, MTOK / 128), 256, GEMM_SMEM>>>(Ob, Wo, out, MTOK, HID, QDIM);
}

// round 4
// speedup vs baseline: 4.5412x; 3.0112x over previous
#include <cuda_runtime.h>
#include <cuda_bf16.h>
#include <math.h>
#include <stdint.h>

// Problem constants
#define BB   2
#define SS   2048
#define HID  2048
#define NH   16
#define NKV  4
#define HD   128
#define MTOK (BB*SS)          // 4096 tokens
#define QDIM (NH*HD)          // 2048
#define KVDIM (NKV*HD)        // 512

// ---------------------------------------------------------------------------
// Scratch (device globals; no allocation allowed)
// ---------------------------------------------------------------------------
__device__ float g_Q[(size_t)MTOK * QDIM];    // fp32 Q pre-rope
__device__ float g_K[(size_t)MTOK * KVDIM];   // fp32 K pre-rope
__device__ float g_V[(size_t)MTOK * KVDIM];   // fp32 V

__device__ __nv_bfloat16 g_Hh[(size_t)MTOK * HID],  g_Hl[(size_t)MTOK * HID];
__device__ __nv_bfloat16 g_Wqh[(size_t)QDIM * HID], g_Wql[(size_t)QDIM * HID];
__device__ __nv_bfloat16 g_Wkh[(size_t)KVDIM * HID], g_Wkl[(size_t)KVDIM * HID];
__device__ __nv_bfloat16 g_Wvh[(size_t)KVDIM * HID], g_Wvl[(size_t)KVDIM * HID];
__device__ __nv_bfloat16 g_Woh[(size_t)HID * QDIM], g_Wol[(size_t)HID * QDIM];
__device__ __nv_bfloat16 g_Qh[(size_t)MTOK * QDIM],  g_Ql[(size_t)MTOK * QDIM];
__device__ __nv_bfloat16 g_Kh[(size_t)MTOK * KVDIM], g_Kl[(size_t)MTOK * KVDIM];
__device__ __nv_bfloat16 g_Vh[(size_t)MTOK * KVDIM], g_Vl[(size_t)MTOK * KVDIM];
__device__ __nv_bfloat16 g_Oh[(size_t)MTOK * QDIM],  g_Ol[(size_t)MTOK * QDIM];

// ---------------------------------------------------------------------------
// helpers
// ---------------------------------------------------------------------------
__device__ __forceinline__ uint32_t smem_to_u32(const void* p) {
    uint32_t a;
    asm("{ .reg .u64 t; cvta.to.shared.u64 t, %1; cvt.u32.u64 %0, t; }"
        : "=r"(a) : "l"(p));
    return a;
}
__device__ __forceinline__ uint32_t pack_bf16(__nv_bfloat16 a, __nv_bfloat16 b) {
    return (uint32_t)__bfloat16_as_ushort(a) |
           ((uint32_t)__bfloat16_as_ushort(b) << 16);
}
// split pair of floats into packed bf16 hi and packed bf16 lo
__device__ __forceinline__ void split2(float a, float b, uint32_t& h, uint32_t& l) {
    __nv_bfloat16 ha = __float2bfloat16_rn(a);
    __nv_bfloat16 hb = __float2bfloat16_rn(b);
    __nv_bfloat16 la = __float2bfloat16_rn(a - __bfloat162float(ha));
    __nv_bfloat16 lb = __float2bfloat16_rn(b - __bfloat162float(hb));
    h = pack_bf16(ha, hb);
    l = pack_bf16(la, lb);
}

#define LDMX4(r, addr) \
    asm volatile("ldmatrix.sync.aligned.m8n8.x4.shared.b16 {%0,%1,%2,%3}, [%4];" \
        : "=r"((r)[0]), "=r"((r)[1]), "=r"((r)[2]), "=r"((r)[3]) : "r"(addr))
#define LDMX4T(r, addr) \
    asm volatile("ldmatrix.sync.aligned.m8n8.x4.trans.shared.b16 {%0,%1,%2,%3}, [%4];" \
        : "=r"((r)[0]), "=r"((r)[1]), "=r"((r)[2]), "=r"((r)[3]) : "r"(addr))
#define MMA_BF16(c, a, b0, b1) \
    asm volatile("mma.sync.aligned.m16n8k16.row.col.f32.bf16.bf16.f32 " \
        "{%0,%1,%2,%3},{%4,%5,%6,%7},{%8,%9},{%0,%1,%2,%3};" \
        : "+f"((c)[0]), "+f"((c)[1]), "+f"((c)[2]), "+f"((c)[3]) \
        : "r"((a)[0]), "r"((a)[1]), "r"((a)[2]), "r"((a)[3]), "r"(b0), "r"(b1))

// ---------------------------------------------------------------------------
// split kernel: fp32 -> (bf16 hi, bf16 lo), vectorized by 4
// ---------------------------------------------------------------------------
__global__ void split_kernel(const float* __restrict__ src,
                             __nv_bfloat16* __restrict__ h,
                             __nv_bfloat16* __restrict__ l, int n4)
{
    int i = blockIdx.x * blockDim.x + threadIdx.x;
    if (i >= n4) return;
    float4 v = ((const float4*)src)[i];
    uint32_t h0, l0, h1, l1;
    split2(v.x, v.y, h0, l0);
    split2(v.z, v.w, h1, l1);
    ((uint2*)h)[i] = make_uint2(h0, h1);
    ((uint2*)l)[i] = make_uint2(l0, l1);
}

// ---------------------------------------------------------------------------
// RoPE + split: reads fp32 X, applies rope, writes bf16 hi/lo
// ---------------------------------------------------------------------------
__global__ void rope_split_kernel(const float* __restrict__ X,
                                  const int* __restrict__ pos_ids, int nheads,
                                  __nv_bfloat16* __restrict__ Xh,
                                  __nv_bfloat16* __restrict__ Xl)
{
    int idx = blockIdx.x * blockDim.x + threadIdx.x;
    if (idx >= MTOK * 64) return;
    int i = idx & 63;
    int m = idx >> 6;
    int p = pos_ids[m];

    double inv = exp(-(double)i * 0.14391156831212787);  // ln(10000)/64
    double ang = (double)p * inv;
    double k = rint(ang * 0.15915494309189535);
    float r = (float)(ang - k * 6.283185307179586477);
    float sv, cv;
    sincosf(r, &sv, &cv);

    size_t base = (size_t)m * (nheads * 128) + i;
#pragma unroll 4
    for (int h = 0; h < nheads; h++) {
        float x1 = X[base], x2 = X[base + 64];
        float y1 = x1 * cv - x2 * sv;
        float y2 = x2 * cv + x1 * sv;
        __nv_bfloat16 h1 = __float2bfloat16_rn(y1);
        __nv_bfloat16 h2 = __float2bfloat16_rn(y2);
        Xh[base]      = h1;
        Xh[base + 64] = h2;
        Xl[base]      = __float2bfloat16_rn(y1 - __bfloat162float(h1));
        Xl[base + 64] = __float2bfloat16_rn(y2 - __bfloat162float(h2));
        base += 128;
    }
}

// ---------------------------------------------------------------------------
// bf16x3 tensor-core GEMM with PRE-SPLIT inputs:
// C[M,N] = (Ah+Al)[M,K] @ (Bh+Bl)[N,K]^T  via Ah*Bh + Ah*Bl + Al*Bh, fp32 out.
// CTA tile 128x128, BK=32, 256 threads (8 warps, warp tile 64x32).
// smem rows padded to 40 bf16; parts Ah|Al|Bh|Bl double buffered.
// ---------------------------------------------------------------------------
#define SROW   40
#define TPART  (128 * SROW * 2)        // 10240 B
#define TSTAGE (4 * TPART)             // 40960 B
#define GEMM_SMEM (2 * TSTAGE)         // 81920 B

__global__ __launch_bounds__(256) void gemm_bf16x3_pre(
    const __nv_bfloat16* __restrict__ Ah, const __nv_bfloat16* __restrict__ Al,
    const __nv_bfloat16* __restrict__ Bh, const __nv_bfloat16* __restrict__ Bl,
    float* __restrict__ C, int M, int N, int K)
{
    extern __shared__ char smem[];
    const uint32_t sbase = smem_to_u32(smem);

    const int tid  = threadIdx.x;
    const int wid  = tid >> 5;
    const int lane = tid & 31;
    const int wm   = wid >> 2;
    const int wn   = wid & 3;
    const int bm   = blockIdx.y * 128;
    const int bn   = blockIdx.x * 128;

    // load mapping: per part 512 uint4 (128 rows x 4), 2 per thread
    const int r0 = tid >> 2;            // g=0 row
    const int c0 = tid & 3;             // uint4 col
    const int r1 = (256 + tid) >> 2;
    const int c1 = c0;

    const int NKT = K / 32;

    float acc[4][4][4];
#pragma unroll
    for (int mf = 0; mf < 4; mf++)
#pragma unroll
        for (int nf = 0; nf < 4; nf++)
#pragma unroll
            for (int r = 0; r < 4; r++) acc[mf][nf][r] = 0.f;

    uint4 rAh[2], rAl[2], rBh[2], rBl[2];

#define G_LDG(kt) do { \
    size_t a0 = (size_t)(bm + r0) * K + (kt) * 32 + c0 * 8; \
    size_t a1 = (size_t)(bm + r1) * K + (kt) * 32 + c1 * 8; \
    size_t b0 = (size_t)(bn + r0) * K + (kt) * 32 + c0 * 8; \
    size_t b1 = (size_t)(bn + r1) * K + (kt) * 32 + c1 * 8; \
    rAh[0] = *(const uint4*)(Ah + a0); rAh[1] = *(const uint4*)(Ah + a1); \
    rAl[0] = *(const uint4*)(Al + a0); rAl[1] = *(const uint4*)(Al + a1); \
    rBh[0] = *(const uint4*)(Bh + b0); rBh[1] = *(const uint4*)(Bh + b1); \
    rBl[0] = *(const uint4*)(Bl + b0); rBl[1] = *(const uint4*)(Bl + b1); \
} while (0)

#define G_STS(buf) do { \
    char* p = smem + (buf) * TSTAGE; \
    int o0 = r0 * (SROW * 2) + c0 * 16; \
    int o1 = r1 * (SROW * 2) + c1 * 16; \
    *(uint4*)(p + o0)             = rAh[0]; *(uint4*)(p + o1)             = rAh[1]; \
    *(uint4*)(p + TPART + o0)     = rAl[0]; *(uint4*)(p + TPART + o1)     = rAl[1]; \
    *(uint4*)(p + 2 * TPART + o0) = rBh[0]; *(uint4*)(p + 2 * TPART + o1) = rBh[1]; \
    *(uint4*)(p + 3 * TPART + o0) = rBl[0]; *(uint4*)(p + 3 * TPART + o1) = rBl[1]; \
} while (0)

    G_LDG(0);
    G_STS(0);
    __syncthreads();

    const int lr16 = lane & 15;
    const int lh   = lane >> 4;
    const uint32_t a_lane = (uint32_t)((wm * 64 + lr16) * (SROW * 2) + lh * 16);
    const uint32_t b_lane = (uint32_t)((wn * 32 + lr16) * (SROW * 2) + lh * 16);

    for (int kt = 0; kt < NKT; kt++) {
        if (kt + 1 < NKT) G_LDG(kt + 1);

        {
            const uint32_t base = sbase + (uint32_t)(kt & 1) * TSTAGE;
#pragma unroll
            for (int ks = 0; ks < 2; ks++) {
                const uint32_t kb = ks * 32;
                uint32_t ah[4][4], al[4][4], bh[2][4], bl[2][4];
#pragma unroll
                for (int mf = 0; mf < 4; mf++)
                    LDMX4(ah[mf], base + a_lane + mf * 16 * (SROW * 2) + kb);
#pragma unroll
                for (int nf2 = 0; nf2 < 2; nf2++)
                    LDMX4(bh[nf2], base + 2 * TPART + b_lane + nf2 * 16 * (SROW * 2) + kb);
#pragma unroll
                for (int mf = 0; mf < 4; mf++)
#pragma unroll
                    for (int nf = 0; nf < 4; nf++)
                        MMA_BF16(acc[mf][nf], ah[mf],
                                 bh[nf >> 1][nf & 1], bh[nf >> 1][(nf & 1) + 2]);
#pragma unroll
                for (int nf2 = 0; nf2 < 2; nf2++)
                    LDMX4(bl[nf2], base + 3 * TPART + b_lane + nf2 * 16 * (SROW * 2) + kb);
#pragma unroll
                for (int mf = 0; mf < 4; mf++)
#pragma unroll
                    for (int nf = 0; nf < 4; nf++)
                        MMA_BF16(acc[mf][nf], ah[mf],
                                 bl[nf >> 1][nf & 1], bl[nf >> 1][(nf & 1) + 2]);
#pragma unroll
                for (int mf = 0; mf < 4; mf++)
                    LDMX4(al[mf], base + TPART + a_lane + mf * 16 * (SROW * 2) + kb);
#pragma unroll
                for (int mf = 0; mf < 4; mf++)
#pragma unroll
                    for (int nf = 0; nf < 4; nf++)
                        MMA_BF16(acc[mf][nf], al[mf],
                                 bh[nf >> 1][nf & 1], bh[nf >> 1][(nf & 1) + 2]);
            }
        }

        if (kt + 1 < NKT) G_STS((kt + 1) & 1);
        __syncthreads();
    }

    const int erow = bm + wm * 64 + (lane >> 2);
    const int ecol = bn + wn * 32 + (lane & 3) * 2;
#pragma unroll
    for (int mf = 0; mf < 4; mf++)
#pragma unroll
        for (int nf = 0; nf < 4; nf++) {
            float* c = acc[mf][nf];
            size_t ro0 = (size_t)(erow + mf * 16) * N + ecol + nf * 8;
            size_t ro1 = ro0 + 8 * (size_t)N;
            *(float2*)(C + ro0) = make_float2(c[0], c[1]);
            *(float2*)(C + ro1) = make_float2(c[2], c[3]);
        }
#undef G_LDG
#undef G_STS
}

// ---------------------------------------------------------------------------
// Tensor-core flash attention, causal, GQA.
// 64 q-rows x 64 kv tiles, 4 warps (16 q-rows each), HD=128.
// QK: Qh*Kh + Ql*Kh + Qh*Kl; PV: Ph*Vh + Pl*Vh + Ph*Vl (all bf16 splits).
// Writes split bf16 output (Oh, Ol) for the downstream Wo GEMM.
// smem: 6 tiles of 64 x 136 bf16 (Qh Ql Kh Kl Vh Vl) = 104448 B.
// ---------------------------------------------------------------------------
#define FROWB 272                      // 136 bf16 per row
#define FTILE (64 * FROWB)             // 17408 B
#define FLASH_SMEM (6 * FTILE)
#define SC_LOG2E 0.12751631762078975f  // (1/sqrt(128)) * log2(e)

__global__ __launch_bounds__(128) void flash_tc(
    const __nv_bfloat16* __restrict__ Qh, const __nv_bfloat16* __restrict__ Ql,
    const __nv_bfloat16* __restrict__ Kh, const __nv_bfloat16* __restrict__ Kl,
    const __nv_bfloat16* __restrict__ Vh, const __nv_bfloat16* __restrict__ Vl,
    __nv_bfloat16* __restrict__ Oh, __nv_bfloat16* __restrict__ Ol)
{
    extern __shared__ char sm[];
    const uint32_t sb = smem_to_u32(sm);
    const uint32_t sQh = sb,             sQl = sb + FTILE;
    const uint32_t sKh = sb + 2 * FTILE, sKl = sb + 3 * FTILE;
    const uint32_t sVh = sb + 4 * FTILE, sVl = sb + 5 * FTILE;

    const int q0  = blockIdx.x * 64;
    const int h   = blockIdx.y;
    const int b   = blockIdx.z;
    const int kvh = h >> 2;
    const int tid  = threadIdx.x;
    const int wid  = tid >> 5;
    const int lane = tid & 31;

    // ---- load Q tile (hi & lo) once
    for (int i = tid; i < 64 * 16; i += 128) {
        int r = i >> 4, c = i & 15;
        size_t g = (size_t)(b * SS + q0 + r) * QDIM + h * HD + c * 8;
        int off = r * FROWB + c * 16;
        *(uint4*)(sm + off)         = *(const uint4*)(Qh + g);
        *(uint4*)(sm + FTILE + off) = *(const uint4*)(Ql + g);
    }

    // ldmatrix lane offsets
    // A-pattern (row bit3, col bit4): for Q fragments and V-trans fragments
    const uint32_t a_off = (uint32_t)((16 * wid + (lane & 7) + 8 * ((lane >> 3) & 1)) * FROWB
                                      + (lane >> 4) * 16);
    const uint32_t vt_off = (uint32_t)(((lane & 7) + 8 * ((lane >> 3) & 1)) * FROWB
                                       + (lane >> 4) * 16);
    // B-pattern (row bit4, col bit3): for K fragments
    const uint32_t b_off = (uint32_t)(((lane & 7) + 8 * (lane >> 4)) * FROWB
                                      + ((lane >> 3) & 1) * 16);

    float o[16][4];
#pragma unroll
    for (int nf = 0; nf < 16; nf++)
#pragma unroll
        for (int r = 0; r < 4; r++) o[nf][r] = 0.f;
    float mo[2] = {-1e30f, -1e30f};
    float ls[2] = {0.f, 0.f};

    const int ntiles = q0 / 64 + 1;
    for (int t = 0; t < ntiles; t++) {
        const int kt = t * 64;
        __syncthreads();   // previous tile's MMAs done with K/V smem
        for (int i = tid; i < 64 * 16; i += 128) {
            int r = i >> 4, c = i & 15;
            size_t g = (size_t)(b * SS + kt + r) * KVDIM + kvh * HD + c * 8;
            int off = r * FROWB + c * 16;
            *(uint4*)(sm + 2 * FTILE + off) = *(const uint4*)(Kh + g);
            *(uint4*)(sm + 3 * FTILE + off) = *(const uint4*)(Kl + g);
            *(uint4*)(sm + 4 * FTILE + off) = *(const uint4*)(Vh + g);
            *(uint4*)(sm + 5 * FTILE + off) = *(const uint4*)(Vl + g);
        }
        __syncthreads();

        // ---- S = Q K^T (3 passes)
        float s[8][4];
#pragma unroll
        for (int f = 0; f < 8; f++)
#pragma unroll
            for (int r = 0; r < 4; r++) s[f][r] = 0.f;

#pragma unroll
        for (int ks = 0; ks < 8; ks++) {
            uint32_t ah[4], al[4];
            LDMX4(ah, sQh + a_off + ks * 32);
            LDMX4(al, sQl + a_off + ks * 32);
#pragma unroll
            for (int nb = 0; nb < 4; nb++) {
                uint32_t kh[4], kl[4];
                LDMX4(kh, sKh + b_off + nb * 16 * FROWB + ks * 32);
                LDMX4(kl, sKl + b_off + nb * 16 * FROWB + ks * 32);
                MMA_BF16(s[2 * nb],     ah, kh[0], kh[1]);
                MMA_BF16(s[2 * nb + 1], ah, kh[2], kh[3]);
                MMA_BF16(s[2 * nb],     al, kh[0], kh[1]);
                MMA_BF16(s[2 * nb + 1], al, kh[2], kh[3]);
                MMA_BF16(s[2 * nb],     ah, kl[0], kl[1]);
                MMA_BF16(s[2 * nb + 1], ah, kl[2], kl[3]);
            }
        }

        // ---- scale (+ causal mask on diagonal tile)
#pragma unroll
        for (int f = 0; f < 8; f++)
#pragma unroll
            for (int r = 0; r < 4; r++) s[f][r] *= SC_LOG2E;

        if (kt == q0) {
            const int row0 = q0 + 16 * wid + (lane >> 2);
            const int colb = kt + 2 * (lane & 3);
#pragma unroll
            for (int f = 0; f < 8; f++)
#pragma unroll
                for (int r = 0; r < 4; r++) {
                    int col = colb + 8 * f + (r & 1);
                    int row = row0 + 8 * (r >> 1);
                    if (col > row) s[f][r] = -1e30f;
                }
        }

        // ---- online softmax (two row-halves per lane)
#pragma unroll
        for (int hh = 0; hh < 2; hh++) {
            float mt = -1e30f;
#pragma unroll
            for (int f = 0; f < 8; f++)
                mt = fmaxf(mt, fmaxf(s[f][2 * hh], s[f][2 * hh + 1]));
            mt = fmaxf(mt, __shfl_xor_sync(0xffffffffu, mt, 1));
            mt = fmaxf(mt, __shfl_xor_sync(0xffffffffu, mt, 2));
            float mn = fmaxf(mo[hh], mt);
            float alpha = exp2f(mo[hh] - mn);
            float rs = 0.f;
#pragma unroll
            for (int f = 0; f < 8; f++) {
                float p0 = exp2f(s[f][2 * hh] - mn);
                float p1 = exp2f(s[f][2 * hh + 1] - mn);
                s[f][2 * hh] = p0;
                s[f][2 * hh + 1] = p1;
                rs += p0 + p1;
            }
            rs += __shfl_xor_sync(0xffffffffu, rs, 1);
            rs += __shfl_xor_sync(0xffffffffu, rs, 2);
            ls[hh] = ls[hh] * alpha + rs;
            mo[hh] = mn;
#pragma unroll
            for (int nf = 0; nf < 16; nf++) {
                o[nf][2 * hh]     *= alpha;
                o[nf][2 * hh + 1] *= alpha;
            }
        }

        // ---- O += P V (3 passes), P packed from registers
#pragma unroll
        for (int ks = 0; ks < 4; ks++) {
            uint32_t ph[4], pl[4];
            split2(s[2 * ks][0],     s[2 * ks][1],     ph[0], pl[0]);
            split2(s[2 * ks][2],     s[2 * ks][3],     ph[1], pl[1]);
            split2(s[2 * ks + 1][0], s[2 * ks + 1][1], ph[2], pl[2]);
            split2(s[2 * ks + 1][2], s[2 * ks + 1][3], ph[3], pl[3]);
#pragma unroll
            for (int nb = 0; nb < 8; nb++) {
                uint32_t vh[4], vl[4];
                LDMX4T(vh, sVh + vt_off + ks * 16 * FROWB + nb * 32);
                LDMX4T(vl, sVl + vt_off + ks * 16 * FROWB + nb * 32);
                MMA_BF16(o[2 * nb],     ph, vh[0], vh[1]);
                MMA_BF16(o[2 * nb + 1], ph, vh[2], vh[3]);
                MMA_BF16(o[2 * nb],     pl, vh[0], vh[1]);
                MMA_BF16(o[2 * nb + 1], pl, vh[2], vh[3]);
                MMA_BF16(o[2 * nb],     ph, vl[0], vl[1]);
                MMA_BF16(o[2 * nb + 1], ph, vl[2], vl[3]);
            }
        }
    }

    // ---- epilogue: normalize, split to bf16 hi/lo, store
    float inv0 = 1.f / ls[0];
    float inv1 = 1.f / ls[1];
#pragma unroll
    for (int nf = 0; nf < 16; nf++) {
#pragma unroll
        for (int rp = 0; rp < 2; rp++) {
            float invv = rp ? inv1 : inv0;
            float v0 = o[nf][2 * rp] * invv;
            float v1 = o[nf][2 * rp + 1] * invv;
            uint32_t hi, lo;
            split2(v0, v1, hi, lo);
            int row = q0 + 16 * wid + (lane >> 2) + 8 * rp;
            int col = h * HD + 8 * nf + 2 * (lane & 3);
            size_t g = (size_t)(b * SS + row) * QDIM + col;
            *(uint32_t*)(Oh + g) = hi;
            *(uint32_t*)(Ol + g) = lo;
        }
    }
}

// ---------------------------------------------------------------------------
// launcher
// ---------------------------------------------------------------------------
extern "C" void kernel_launch(void* const* d_in, const int* in_sizes, int n_in,
                              void* d_out, int out_size)
{
    const float* hidden = (const float*)d_in[0];
    const float* Wq     = (const float*)d_in[1];
    const float* Wk     = (const float*)d_in[2];
    const float* Wv     = (const float*)d_in[3];
    const float* Wo     = (const float*)d_in[4];
    const int*   pos    = (const int*)d_in[5];
    float* out = (float*)d_out;

    float *Qb, *Kb, *Vb;
    cudaGetSymbolAddress((void**)&Qb, g_Q);
    cudaGetSymbolAddress((void**)&Kb, g_K);
    cudaGetSymbolAddress((void**)&Vb, g_V);

    __nv_bfloat16 *Hh, *Hl, *Wqh, *Wql, *Wkh, *Wkl, *Wvh, *Wvl, *Woh, *Wol;
    __nv_bfloat16 *Qh, *Ql, *Kh, *Kl, *Vh, *Vl, *Ohb, *Olb;
    cudaGetSymbolAddress((void**)&Hh, g_Hh);   cudaGetSymbolAddress((void**)&Hl, g_Hl);
    cudaGetSymbolAddress((void**)&Wqh, g_Wqh); cudaGetSymbolAddress((void**)&Wql, g_Wql);
    cudaGetSymbolAddress((void**)&Wkh, g_Wkh); cudaGetSymbolAddress((void**)&Wkl, g_Wkl);
    cudaGetSymbolAddress((void**)&Wvh, g_Wvh); cudaGetSymbolAddress((void**)&Wvl, g_Wvl);
    cudaGetSymbolAddress((void**)&Woh, g_Woh); cudaGetSymbolAddress((void**)&Wol, g_Wol);
    cudaGetSymbolAddress((void**)&Qh, g_Qh);   cudaGetSymbolAddress((void**)&Ql, g_Ql);
    cudaGetSymbolAddress((void**)&Kh, g_Kh);   cudaGetSymbolAddress((void**)&Kl, g_Kl);
    cudaGetSymbolAddress((void**)&Vh, g_Vh);   cudaGetSymbolAddress((void**)&Vl, g_Vl);
    cudaGetSymbolAddress((void**)&Ohb, g_Oh);  cudaGetSymbolAddress((void**)&Olb, g_Ol);

    cudaFuncSetAttribute(gemm_bf16x3_pre,
                         cudaFuncAttributeMaxDynamicSharedMemorySize, GEMM_SMEM);
    cudaFuncSetAttribute(flash_tc,
                         cudaFuncAttributeMaxDynamicSharedMemorySize, FLASH_SMEM);

    // 1. split inputs to bf16 hi/lo
    split_kernel<<<(MTOK * HID / 4 + 255) / 256, 256>>>(hidden, Hh, Hl, MTOK * HID / 4);
    split_kernel<<<(QDIM * HID / 4 + 255) / 256, 256>>>(Wq, Wqh, Wql, QDIM * HID / 4);
    split_kernel<<<(KVDIM * HID / 4 + 255) / 256, 256>>>(Wk, Wkh, Wkl, KVDIM * HID / 4);
    split_kernel<<<(KVDIM * HID / 4 + 255) / 256, 256>>>(Wv, Wvh, Wvl, KVDIM * HID / 4);
    split_kernel<<<(HID * QDIM / 4 + 255) / 256, 256>>>(Wo, Woh, Wol, HID * QDIM / 4);

    // 2. QKV projections (fp32 out)
    gemm_bf16x3_pre<<<dim3(QDIM / 128, MTOK / 128), 256, GEMM_SMEM>>>(
        Hh, Hl, Wqh, Wql, Qb, MTOK, QDIM, HID);
    gemm_bf16x3_pre<<<dim3(KVDIM / 128, MTOK / 128), 256, GEMM_SMEM>>>(
        Hh, Hl, Wkh, Wkl, Kb, MTOK, KVDIM, HID);
    gemm_bf16x3_pre<<<dim3(KVDIM / 128, MTOK / 128), 256, GEMM_SMEM>>>(
        Hh, Hl, Wvh, Wvl, Vb, MTOK, KVDIM, HID);

    // 3. RoPE + split Q/K; split V
    rope_split_kernel<<<(MTOK * 64) / 256, 256>>>(Qb, pos, NH, Qh, Ql);
    rope_split_kernel<<<(MTOK * 64) / 256, 256>>>(Kb, pos, NKV, Kh, Kl);
    split_kernel<<<(MTOK * KVDIM / 4 + 255) / 256, 256>>>(Vb, Vh, Vl, MTOK * KVDIM / 4);

    // 4. flash attention (tensor cores), split bf16 out
    flash_tc<<<dim3(SS / 64, NH, BB), 128, FLASH_SMEM>>>(
        Qh, Ql, Kh, Kl, Vh, Vl, Ohb, Olb);

    // 5. output projection
    gemm_bf16x3_pre<<<dim3(HID / 128, MTOK / 128), 256, GEMM_SMEM>>>(
        Ohb, Olb, Woh, Wol, out, MTOK, HID, QDIM);
}